// round 11
// baseline (speedup 1.0000x reference)
#include <cuda_runtime.h>
#include <cuda_bf16.h>

// ---------------- problem constants ----------------
#define N_WORDS   4096
#define WORD_LEN  16
#define GLOVE_DIM 300
#define CHAR_EMB  50
#define CHAR_HID  128
#define G4        512           // 4*CHAR_HID
#define HIDDEN    512
#define FEAT      428           // GLOVE_DIM + CHAR_HID
#define WPB       32            // words per block
#define NBLK      (N_WORDS / WPB)   // 128
#define HSTRIDE   34            // padded h row stride (floats)

typedef unsigned long long ull;

// ---------------- device scratch (static; no allocations allowed) ----------------
// weights: [k][p][n] as ulonglong2, p=0 -> {i,i,f,f}, p=1 -> {g,g,o,o}
__device__ ulonglong2 g_Wih4[CHAR_EMB * 2 * CHAR_HID];
__device__ ulonglong2 g_Whh4[CHAR_HID * 2 * CHAR_HID];
__device__ float g_bsum[G4];                // b_ih + b_hh
__device__ float g_Gpart[NBLK * GLOVE_DIM];
__device__ float g_Hpart[NBLK * CHAR_HID];
__device__ float g_avg[FEAT];
__device__ float g_hid[HIDDEN];

// ---------------- packed f32x2 helpers ----------------
static __device__ __forceinline__ ull pack2(float lo, float hi) {
    ull r;
    asm("mov.b64 %0, {%1, %2};" : "=l"(r) : "f"(lo), "f"(hi));
    return r;
}
static __device__ __forceinline__ void unpack2(ull v, float &lo, float &hi) {
    asm("mov.b64 {%0, %1}, %2;" : "=f"(lo), "=f"(hi) : "l"(v));
}
static __device__ __forceinline__ void ffma2(ull &d, ull a, ull b) {
    asm("fma.rn.f32x2 %0, %1, %2, %0;" : "+l"(d) : "l"(a), "l"(b));
}
static __device__ __forceinline__ float ex2f(float x) {
    float r; asm("ex2.approx.f32 %0, %1;" : "=f"(r) : "f"(x)); return r;
}
static __device__ __forceinline__ float rcpf(float x) {
    float r; asm("rcp.approx.f32 %0, %1;" : "=f"(r) : "f"(x)); return r;
}
#define L2E 1.4426950408889634f

// ---------------- prep: transpose + duplicate weights, fold bias ----------------
__global__ void prep_kernel(const float* __restrict__ W_ih,
                            const float* __restrict__ W_hh,
                            const float* __restrict__ b_ih,
                            const float* __restrict__ b_hh) {
    int gid = blockIdx.x * blockDim.x + threadIdx.x;
    int stride = gridDim.x * blockDim.x;
    for (int i = gid; i < G4 * CHAR_EMB; i += stride) {
        int j = i / CHAR_EMB, k = i % CHAR_EMB;
        int gate = j >> 7, n = j & 127;
        float w = W_ih[i];
        ull* dst = reinterpret_cast<ull*>(&g_Wih4[(k * 2 + (gate >> 1)) * CHAR_HID + n]);
        dst[gate & 1] = pack2(w, w);
    }
    for (int i = gid; i < G4 * CHAR_HID; i += stride) {
        int j = i >> 7, k = i & 127;
        int gate = j >> 7, n = j & 127;
        float w = W_hh[i];
        ull* dst = reinterpret_cast<ull*>(&g_Whh4[(k * 2 + (gate >> 1)) * CHAR_HID + n]);
        dst[gate & 1] = pack2(w, w);
    }
    for (int i = gid; i < G4; i += stride)
        g_bsum[i] = b_ih[i] + b_hh[i];
}

// ---------------- glove partial sums ----------------
__global__ void glove_kernel(const int* __restrict__ wid,
                             const float* __restrict__ table) {
    __shared__ int idx[WPB];
    int tid = threadIdx.x;
    if (tid < WPB) idx[tid] = wid[blockIdx.x * WPB + tid];
    __syncthreads();
    if (tid < GLOVE_DIM) {
        float s = 0.0f;
        #pragma unroll 8
        for (int w = 0; w < WPB; w++)
            s += __ldg(table + (long)idx[w] * GLOVE_DIM + tid);
        g_Gpart[blockIdx.x * GLOVE_DIM + tid] = s;
    }
}

// ---------------- char LSTM: 32 words per block, 1024 threads ----------------
// tid = grp*128 + n, grp in 0..7.  Thread owns hidden unit n for its group's
// 4 words (2 f32x2 word-pairs), all 4 gates, via fma.rn.f32x2.
__global__ __launch_bounds__(1024, 1)
void lstm_kernel(const int* __restrict__ char_idx,
                 const float* __restrict__ cemb) {
    extern __shared__ float sm[];
    float* xT   = sm;                                          // [t][k][w]  16*50*32
    float* hbufA = sm + WORD_LEN * CHAR_EMB * WPB;             // [128][HSTRIDE]
    float* hbufB = hbufA + CHAR_HID * HSTRIDE;                 // [128][HSTRIDE]
    float* ssum = hbufB + CHAR_HID * HSTRIDE;                  // [1024]

    const int tid = threadIdx.x;
    const int n   = tid & (CHAR_HID - 1);
    const int grp = tid >> 7;                                  // 0..7
    const int w0  = blockIdx.x * WPB;

    // gather all char embeddings, transposed to [t][k][w]
    // 512 (w,t) items, 2 threads each: half 0 -> k2 [0,13), half 1 -> k2 [13,25)
    {
        int p    = tid >> 1;            // 0..511
        int half = tid & 1;
        int w = p & (WPB - 1);
        int t = p >> 5;
        int ci = char_idx[(w0 + w) * WORD_LEN + t];
        const float2* src = reinterpret_cast<const float2*>(cemb + ci * CHAR_EMB);
        float* dst = xT + (t * CHAR_EMB) * WPB + w;
        int k2beg = half ? 13 : 0;
        int k2end = half ? 25 : 13;
        for (int k2 = k2beg; k2 < k2end; k2++) {
            float2 v = __ldg(&src[k2]);
            dst[(2 * k2) * WPB]     = v.x;
            dst[(2 * k2 + 1) * WPB] = v.y;
        }
    }

    const float bi_s = g_bsum[n];
    const float bf_s = g_bsum[n + 128];
    const float bg_s = g_bsum[n + 256];
    const float bo_s = g_bsum[n + 384];

    float c[4];
    #pragma unroll
    for (int j = 0; j < 4; j++) c[j] = 0.0f;
    float hval[4];

    __syncthreads();

    for (int t = 0; t < WORD_LEN; t++) {
        float* rbuf = (t & 1) ? hbufA : hbufB;   // written at step t-1
        float* wbuf = (t & 1) ? hbufB : hbufA;

        ull acc[2][4];
        #pragma unroll
        for (int j = 0; j < 2; j++)
            #pragma unroll
            for (int q = 0; q < 4; q++) acc[j][q] = 0ULL;

        // ---- x @ W_ih^T ----
        {
            const float* xbase = xT + (t * CHAR_EMB) * WPB + grp * 4;
            const ulonglong2* Wp = g_Wih4 + n;
            #pragma unroll 10
            for (int k = 0; k < CHAR_EMB; k++) {
                ulonglong2 wif = __ldg(Wp + (2 * k) * CHAR_HID);
                ulonglong2 wgo = __ldg(Wp + (2 * k + 1) * CHAR_HID);
                const ull* xp = reinterpret_cast<const ull*>(xbase + k * WPB);
                #pragma unroll
                for (int j = 0; j < 2; j++) {
                    ull x2 = xp[j];
                    ffma2(acc[j][0], wif.x, x2);
                    ffma2(acc[j][1], wif.y, x2);
                    ffma2(acc[j][2], wgo.x, x2);
                    ffma2(acc[j][3], wgo.y, x2);
                }
            }
        }
        // ---- h @ W_hh^T (h == 0 at t==0, skip) ----
        if (t) {
            const ull* hp = reinterpret_cast<const ull*>(rbuf + grp * 4);
            const ulonglong2* Wp = g_Whh4 + n;
            #pragma unroll 8
            for (int k = 0; k < CHAR_HID; k++) {
                ulonglong2 wif = __ldg(Wp + (2 * k) * CHAR_HID);
                ulonglong2 wgo = __ldg(Wp + (2 * k + 1) * CHAR_HID);
                ull h0 = hp[k * (HSTRIDE / 2)];
                ull h1 = hp[k * (HSTRIDE / 2) + 1];
                ffma2(acc[0][0], wif.x, h0);
                ffma2(acc[0][1], wif.y, h0);
                ffma2(acc[0][2], wgo.x, h0);
                ffma2(acc[0][3], wgo.y, h0);
                ffma2(acc[1][0], wif.x, h1);
                ffma2(acc[1][1], wif.y, h1);
                ffma2(acc[1][2], wgo.x, h1);
                ffma2(acc[1][3], wgo.y, h1);
            }
        }

        // ---- activations: merged-divide form, 8 MUFU / word ----
        #pragma unroll
        for (int j = 0; j < 2; j++) {
            float iv0, iv1, fv0, fv1, gv0, gv1, ov0, ov1;
            unpack2(acc[j][0], iv0, iv1);
            unpack2(acc[j][1], fv0, fv1);
            unpack2(acc[j][2], gv0, gv1);
            unpack2(acc[j][3], ov0, ov1);
            #pragma unroll
            for (int q = 0; q < 2; q++) {
                float iv = q ? iv1 : iv0, fv = q ? fv1 : fv0;
                float gv = q ? gv1 : gv0, ov = q ? ov1 : ov0;
                iv += bi_s; fv += bf_s; gv += bg_s; ov += bo_s;
                int w = 2 * j + q;
                float ef = ex2f(-fv * L2E);
                float ei = ex2f(-iv * L2E);
                float eg = ex2f(gv * (2.0f * L2E));
                float eo = ex2f(-ov * L2E);
                float cc = c[w] * rcpf(1.0f + ef)
                         + (eg - 1.0f) * rcpf((1.0f + ei) * (eg + 1.0f));
                c[w] = cc;
                float ec = ex2f(cc * (2.0f * L2E));
                hval[w] = (ec - 1.0f) * rcpf((1.0f + eo) * (ec + 1.0f));
            }
        }

        if (t + 1 < WORD_LEN) {
            ull* hw = reinterpret_cast<ull*>(wbuf + n * HSTRIDE + grp * 4);
            hw[0] = pack2(hval[0], hval[1]);
            hw[1] = pack2(hval[2], hval[3]);
        }
        __syncthreads();   // writes visible before next step's reads
    }

    // per-block partial sum of final h over the 32 words
    float s = hval[0] + hval[1] + hval[2] + hval[3];
    ssum[tid] = s;
    __syncthreads();
    if (tid < CHAR_HID) {
        float acc = 0.0f;
        #pragma unroll
        for (int g = 0; g < 8; g++) acc += ssum[tid + 128 * g];
        g_Hpart[blockIdx.x * CHAR_HID + tid] = acc;
    }
}

// ---------------- avg: one warp per feature ----------------
__global__ __launch_bounds__(128)
void avg_kernel() {
    int f    = blockIdx.x * 4 + (threadIdx.x >> 5);   // 0..427
    int lane = threadIdx.x & 31;
    float s = 0.0f;
    if (f < GLOVE_DIM) {
        #pragma unroll
        for (int b = lane; b < NBLK; b += 32) s += g_Gpart[b * GLOVE_DIM + f];
    } else {
        int nn = f - GLOVE_DIM;
        #pragma unroll
        for (int b = lane; b < NBLK; b += 32) s += g_Hpart[b * CHAR_HID + nn];
    }
    #pragma unroll
    for (int off = 16; off > 0; off >>= 1)
        s += __shfl_down_sync(0xFFFFFFFFu, s, off);
    if (lane == 0)
        g_avg[f] = s * (1.0f / N_WORDS);
}

// ---------------- fc1 + relu: one warp per hidden unit ----------------
__global__ __launch_bounds__(256)
void fc1_kernel(const float* __restrict__ fc1_w,
                const float* __restrict__ fc1_b) {
    int warp = (blockIdx.x * blockDim.x + threadIdx.x) >> 5;  // 0..511
    int lane = threadIdx.x & 31;
    const float* wrow = fc1_w + warp * FEAT;
    float acc = 0.0f;
    #pragma unroll
    for (int d = lane; d < FEAT; d += 32)
        acc = fmaf(g_avg[d], __ldg(wrow + d), acc);
    #pragma unroll
    for (int off = 16; off > 0; off >>= 1)
        acc += __shfl_down_sync(0xFFFFFFFFu, acc, off);
    if (lane == 0)
        g_hid[warp] = fmaxf(acc + fc1_b[warp], 0.0f);
}

// ---------------- fc2 ----------------
__global__ void fc2_kernel(const float* __restrict__ fc2_w,
                           const float* __restrict__ fc2_b,
                           float* __restrict__ out) {
    __shared__ float red0[HIDDEN];
    __shared__ float red1[HIDDEN];
    int tid = threadIdx.x;  // 512 threads
    float h = g_hid[tid];
    red0[tid] = h * fc2_w[tid];
    red1[tid] = h * fc2_w[HIDDEN + tid];
    __syncthreads();
    for (int s = 256; s > 0; s >>= 1) {
        if (tid < s) {
            red0[tid] += red0[tid + s];
            red1[tid] += red1[tid + s];
        }
        __syncthreads();
    }
    if (tid == 0) {
        out[0] = red0[0] + fc2_b[0];
        out[1] = red1[0] + fc2_b[1];
    }
}

// ---------------- launch ----------------
extern "C" void kernel_launch(void* const* d_in, const int* in_sizes, int n_in,
                              void* d_out, int out_size) {
    const int*   word_idx = (const int*)  d_in[0];
    const int*   char_idx = (const int*)  d_in[1];
    const float* glove    = (const float*)d_in[2];
    const float* cemb     = (const float*)d_in[3];
    const float* W_ih     = (const float*)d_in[4];
    const float* W_hh     = (const float*)d_in[5];
    const float* b_ih     = (const float*)d_in[6];
    const float* b_hh     = (const float*)d_in[7];
    const float* fc1_w    = (const float*)d_in[8];
    const float* fc1_b    = (const float*)d_in[9];
    const float* fc2_w    = (const float*)d_in[10];
    const float* fc2_b    = (const float*)d_in[11];
    float* out = (float*)d_out;

    const int smem_bytes =
        (WORD_LEN * CHAR_EMB * WPB + 2 * CHAR_HID * HSTRIDE + 1024) * (int)sizeof(float);
    cudaFuncSetAttribute(lstm_kernel,
                         cudaFuncAttributeMaxDynamicSharedMemorySize, smem_bytes);

    prep_kernel<<<128, 256>>>(W_ih, W_hh, b_ih, b_hh);
    glove_kernel<<<NBLK, 320>>>(word_idx, glove);
    lstm_kernel<<<NBLK, 1024, smem_bytes>>>(char_idx, cemb);
    avg_kernel<<<107, 128>>>();
    fc1_kernel<<<64, 256>>>(fc1_w, fc1_b);
    fc2_kernel<<<1, 512>>>(fc2_w, fc2_b, out);
}

// round 12
// speedup vs baseline: 1.7352x; 1.7352x over previous
#include <cuda_runtime.h>
#include <cuda_bf16.h>
#include <cstdint>

// ---------------- problem constants ----------------
#define N_WORDS   4096
#define WORD_LEN  16
#define GLOVE_DIM 300
#define CHAR_EMB  50
#define CHAR_HID  128
#define G4        512           // 4*CHAR_HID
#define HIDDEN    512
#define FEAT      428           // GLOVE_DIM + CHAR_HID
#define WPB       32            // words per block
#define NBLK      (N_WORDS / WPB)   // 128
#define KTOT      178           // CHAR_EMB + CHAR_HID
#define XH_STRIDE 36            // padded row stride of xh (floats), 16B-aligned rows
#define KT        32            // full k-tile
#define KLAST     18            // 178 = 5*32 + 18 ; and 50 = 32 + 18

typedef unsigned long long ull;

// ---------------- device scratch (static; no allocations allowed) ----------------
__device__ float4 g_Wcat[KTOT * CHAR_HID];  // [k][n] -> {wi, wf, wg, wo} fp32
__device__ float  g_bsum[G4];               // b_ih + b_hh
__device__ float  g_Gpart[NBLK * GLOVE_DIM];
__device__ float  g_Hpart[NBLK * CHAR_HID];
__device__ float  g_avg[FEAT];
__device__ float  g_hid[HIDDEN];

// ---------------- helpers ----------------
static __device__ __forceinline__ ull pack2(float lo, float hi) {
    ull r;
    asm("mov.b64 %0, {%1, %2};" : "=l"(r) : "f"(lo), "f"(hi));
    return r;
}
static __device__ __forceinline__ void unpack2(ull v, float &lo, float &hi) {
    asm("mov.b64 {%0, %1}, %2;" : "=f"(lo), "=f"(hi) : "l"(v));
}
static __device__ __forceinline__ void ffma2(ull &d, ull a, ull b) {
    asm("fma.rn.f32x2 %0, %1, %2, %0;" : "+l"(d) : "l"(a), "l"(b));
}
static __device__ __forceinline__ float ex2f(float x) {
    float r; asm("ex2.approx.f32 %0, %1;" : "=f"(r) : "f"(x)); return r;
}
static __device__ __forceinline__ float rcpf(float x) {
    float r; asm("rcp.approx.f32 %0, %1;" : "=f"(r) : "f"(x)); return r;
}
#define L2E 1.4426950408889634f

#define CP_ASYNC16(dst_u32, gptr) \
    asm volatile("cp.async.cg.shared.global [%0], [%1], 16;" :: "r"(dst_u32), "l"(gptr))
#define CP_COMMIT() asm volatile("cp.async.commit_group;")
#define CP_WAIT0()  asm volatile("cp.async.wait_group 0;")
#define CP_WAIT1()  asm volatile("cp.async.wait_group 1;")

// ---------------- prep: build Wcat [k][n][gate], fold bias ----------------
__global__ void prep_kernel(const float* __restrict__ W_ih,
                            const float* __restrict__ W_hh,
                            const float* __restrict__ b_ih,
                            const float* __restrict__ b_hh) {
    int gid = blockIdx.x * blockDim.x + threadIdx.x;
    int stride = gridDim.x * blockDim.x;
    float* wc = reinterpret_cast<float*>(g_Wcat);
    for (int i = gid; i < KTOT * G4; i += stride) {
        int k = i >> 9;            // 0..177
        int j = i & 511;
        int n = j >> 2, gate = j & 3;
        float v = (k < CHAR_EMB)
                ? W_ih[(gate * CHAR_HID + n) * CHAR_EMB + k]
                : W_hh[(gate * CHAR_HID + n) * CHAR_HID + (k - CHAR_EMB)];
        wc[i] = v;
    }
    for (int i = gid; i < G4; i += stride)
        g_bsum[i] = b_ih[i] + b_hh[i];
}

// ---------------- glove partial sums ----------------
__global__ void glove_kernel(const int* __restrict__ wid,
                             const float* __restrict__ table) {
    __shared__ int idx[WPB];
    int tid = threadIdx.x;
    if (tid < WPB) idx[tid] = wid[blockIdx.x * WPB + tid];
    __syncthreads();
    if (tid < GLOVE_DIM) {
        float s = 0.0f;
        #pragma unroll 8
        for (int w = 0; w < WPB; w++)
            s += __ldg(table + (long)idx[w] * GLOVE_DIM + tid);
        g_Gpart[blockIdx.x * GLOVE_DIM + tid] = s;
    }
}

// ---------------- LSTM helpers ----------------
static __device__ __forceinline__ void issue_tile(int k0, int kcnt, uint32_t dst_u32, int tid) {
    const float4* src = g_Wcat + k0 * CHAR_HID;
    int nf4 = kcnt * CHAR_HID;
    for (int i = tid; i < nf4; i += 512)
        CP_ASYNC16(dst_u32 + i * 16, src + i);
}

template<int KCNT>
static __device__ __forceinline__ void compute_tile(const float4* __restrict__ wt,
                                                    const float* __restrict__ xrow,
                                                    ull acc[4][4]) {
    #pragma unroll
    for (int kk = 0; kk < KCNT; kk++) {
        float4 w4 = wt[kk * CHAR_HID];                       // LDS.128, conflict-free
        ull wi2 = pack2(w4.x, w4.x), wf2 = pack2(w4.y, w4.y);
        ull wg2 = pack2(w4.z, w4.z), wo2 = pack2(w4.w, w4.w);
        ulonglong2 xa = *reinterpret_cast<const ulonglong2*>(xrow + kk * XH_STRIDE);     // bcast
        ulonglong2 xb = *reinterpret_cast<const ulonglong2*>(xrow + kk * XH_STRIDE + 4); // bcast
        ffma2(acc[0][0], wi2, xa.x); ffma2(acc[0][1], wf2, xa.x);
        ffma2(acc[0][2], wg2, xa.x); ffma2(acc[0][3], wo2, xa.x);
        ffma2(acc[1][0], wi2, xa.y); ffma2(acc[1][1], wf2, xa.y);
        ffma2(acc[1][2], wg2, xa.y); ffma2(acc[1][3], wo2, xa.y);
        ffma2(acc[2][0], wi2, xb.x); ffma2(acc[2][1], wf2, xb.x);
        ffma2(acc[2][2], wg2, xb.x); ffma2(acc[2][3], wo2, xb.x);
        ffma2(acc[3][0], wi2, xb.y); ffma2(acc[3][1], wf2, xb.y);
        ffma2(acc[3][2], wg2, xb.y); ffma2(acc[3][3], wo2, xb.y);
    }
}

// ---------------- char LSTM: 32 words/block, 512 threads, smem-tiled weights ----------------
// tid = grp*128 + n, grp 0..3. Thread owns hidden unit n for its group's 8 words.
__global__ __launch_bounds__(512, 1)
void lstm_kernel(const int* __restrict__ char_idx,
                 const float* __restrict__ cemb) {
    extern __shared__ float sm[];
    float* xh  = sm;                                    // [KTOT][XH_STRIDE]: k<50 = x(t), k>=50 = h
    float* wb0 = sm + KTOT * XH_STRIDE;                 // weight tile buf 0: KT*128 float4
    float* wb1 = wb0 + KT * CHAR_HID * 4;               // weight tile buf 1
    int*   scidx = reinterpret_cast<int*>(wb1 + KT * CHAR_HID * 4);  // [t][w] 512 ints
    float* ssum  = reinterpret_cast<float*>(scidx + 512);            // [512]

    const int tid = threadIdx.x;
    const int n   = tid & (CHAR_HID - 1);
    const int grp = tid >> 7;                           // 0..3
    const int w0  = blockIdx.x * WPB;

    // char indices -> smem, [t][w]
    {
        int w = tid >> 4, t = tid & 15;
        scidx[t * 32 + w] = char_idx[(w0 + w) * WORD_LEN + t];
    }

    // fixed per-thread gather assignments for the per-step x gather (1600 items)
    int gw[4], gk[4], gcnt = 0;
    #pragma unroll
    for (int j = 0; j < 4; j++) {
        int idx = tid + 512 * j;
        if (idx < WPB * CHAR_EMB) { gw[gcnt] = idx / CHAR_EMB; gk[gcnt] = idx % CHAR_EMB; gcnt++; }
    }

    const float bi_s = g_bsum[n];
    const float bf_s = g_bsum[n + 128];
    const float bg_s = g_bsum[n + 256];
    const float bo_s = g_bsum[n + 384];

    const uint32_t wbu[2] = { (uint32_t)__cvta_generic_to_shared(wb0),
                              (uint32_t)__cvta_generic_to_shared(wb1) };
    const float4* wbp[2] = { reinterpret_cast<const float4*>(wb0),
                             reinterpret_cast<const float4*>(wb1) };

    float c[8], hval[8];
    #pragma unroll
    for (int j = 0; j < 8; j++) c[j] = 0.0f;

    __syncthreads();   // scidx visible

    for (int t = 0; t < WORD_LEN; t++) {
        const int ntiles = t ? 6 : 2;   // t=0: x only (50 = 32+18); else 178 = 5*32+18

        // prefetch tile 0 (always a full 32-tile)
        issue_tile(0, KT, wbu[0], tid);
        CP_COMMIT();

        // gather x(t) from the L1-resident char-embedding table
        {
            const int* ct = scidx + t * 32;
            #pragma unroll
            for (int j = 0; j < 4; j++)
                if (j < gcnt)
                    xh[gk[j] * XH_STRIDE + gw[j]] =
                        __ldg(cemb + ct[gw[j]] * CHAR_EMB + gk[j]);
        }

        ull acc[4][4];
        #pragma unroll
        for (int j = 0; j < 4; j++)
            #pragma unroll
            for (int q = 0; q < 4; q++) acc[j][q] = 0ULL;

        int buf = 0;
        for (int i = 0; i < ntiles; i++) {
            const bool last = (i == ntiles - 1);
            if (!last) {
                int kcnt_n = (i + 1 == ntiles - 1) ? KLAST : KT;
                issue_tile((i + 1) * KT, kcnt_n, wbu[buf ^ 1], tid);
                CP_COMMIT();
                CP_WAIT1();      // tile i landed (tile i+1 may be in flight)
            } else {
                CP_WAIT0();
            }
            __syncthreads();     // tile i (and gather at i==0) visible to all

            const float* xrow = xh + i * KT * XH_STRIDE + grp * 8;
            const float4* wt = wbp[buf] + n;
            if (last) compute_tile<KLAST>(wt, xrow, acc);
            else      compute_tile<KT>(wt, xrow, acc);
            buf ^= 1;
            if (!last) __syncthreads();  // all done reading old buffer before it is refilled
        }
        __syncthreads();   // all reads of xh (incl. h rows) complete before h overwrite

        // ---- activations: merged-divide form, 8 MUFU / word ----
        #pragma unroll
        for (int j = 0; j < 4; j++) {
            float iv0, iv1, fv0, fv1, gv0, gv1, ov0, ov1;
            unpack2(acc[j][0], iv0, iv1);
            unpack2(acc[j][1], fv0, fv1);
            unpack2(acc[j][2], gv0, gv1);
            unpack2(acc[j][3], ov0, ov1);
            #pragma unroll
            for (int q = 0; q < 2; q++) {
                float iv = q ? iv1 : iv0, fv = q ? fv1 : fv0;
                float gv = q ? gv1 : gv0, ov = q ? ov1 : ov0;
                iv += bi_s; fv += bf_s; gv += bg_s; ov += bo_s;
                int w = 2 * j + q;
                float ef = ex2f(-fv * L2E);
                float ei = ex2f(-iv * L2E);
                float eg = ex2f(gv * (2.0f * L2E));
                float eo = ex2f(-ov * L2E);
                float cc = c[w] * rcpf(1.0f + ef)
                         + (eg - 1.0f) * rcpf((1.0f + ei) * (eg + 1.0f));
                c[w] = cc;
                float ec = ex2f(cc * (2.0f * L2E));
                hval[w] = (ec - 1.0f) * rcpf((1.0f + eo) * (ec + 1.0f));
            }
        }

        if (t + 1 < WORD_LEN) {
            float4* hw = reinterpret_cast<float4*>(xh + (CHAR_EMB + n) * XH_STRIDE + grp * 8);
            hw[0] = make_float4(hval[0], hval[1], hval[2], hval[3]);
            hw[1] = make_float4(hval[4], hval[5], hval[6], hval[7]);
        }
        __syncthreads();   // h visible (and x rows free to regather) before next step
    }

    // per-block partial sum of final h over the 32 words
    float s = hval[0] + hval[1] + hval[2] + hval[3]
            + hval[4] + hval[5] + hval[6] + hval[7];
    ssum[tid] = s;
    __syncthreads();
    if (tid < CHAR_HID)
        g_Hpart[blockIdx.x * CHAR_HID + tid] =
            ssum[tid] + ssum[tid + 128] + ssum[tid + 256] + ssum[tid + 384];
}

// ---------------- avg: one warp per feature ----------------
__global__ __launch_bounds__(128)
void avg_kernel() {
    int f    = blockIdx.x * 4 + (threadIdx.x >> 5);   // 0..427
    int lane = threadIdx.x & 31;
    float s = 0.0f;
    if (f < GLOVE_DIM) {
        #pragma unroll
        for (int b = lane; b < NBLK; b += 32) s += g_Gpart[b * GLOVE_DIM + f];
    } else {
        int nn = f - GLOVE_DIM;
        #pragma unroll
        for (int b = lane; b < NBLK; b += 32) s += g_Hpart[b * CHAR_HID + nn];
    }
    #pragma unroll
    for (int off = 16; off > 0; off >>= 1)
        s += __shfl_down_sync(0xFFFFFFFFu, s, off);
    if (lane == 0)
        g_avg[f] = s * (1.0f / N_WORDS);
}

// ---------------- fc1 + relu: one warp per hidden unit ----------------
__global__ __launch_bounds__(256)
void fc1_kernel(const float* __restrict__ fc1_w,
                const float* __restrict__ fc1_b) {
    int warp = (blockIdx.x * blockDim.x + threadIdx.x) >> 5;  // 0..511
    int lane = threadIdx.x & 31;
    const float* wrow = fc1_w + warp * FEAT;
    float acc = 0.0f;
    #pragma unroll
    for (int d = lane; d < FEAT; d += 32)
        acc = fmaf(g_avg[d], __ldg(wrow + d), acc);
    #pragma unroll
    for (int off = 16; off > 0; off >>= 1)
        acc += __shfl_down_sync(0xFFFFFFFFu, acc, off);
    if (lane == 0)
        g_hid[warp] = fmaxf(acc + fc1_b[warp], 0.0f);
}

// ---------------- fc2 ----------------
__global__ void fc2_kernel(const float* __restrict__ fc2_w,
                           const float* __restrict__ fc2_b,
                           float* __restrict__ out) {
    __shared__ float red0[HIDDEN];
    __shared__ float red1[HIDDEN];
    int tid = threadIdx.x;  // 512 threads
    float h = g_hid[tid];
    red0[tid] = h * fc2_w[tid];
    red1[tid] = h * fc2_w[HIDDEN + tid];
    __syncthreads();
    for (int s = 256; s > 0; s >>= 1) {
        if (tid < s) {
            red0[tid] += red0[tid + s];
            red1[tid] += red1[tid + s];
        }
        __syncthreads();
    }
    if (tid == 0) {
        out[0] = red0[0] + fc2_b[0];
        out[1] = red1[0] + fc2_b[1];
    }
}

// ---------------- launch ----------------
extern "C" void kernel_launch(void* const* d_in, const int* in_sizes, int n_in,
                              void* d_out, int out_size) {
    const int*   word_idx = (const int*)  d_in[0];
    const int*   char_idx = (const int*)  d_in[1];
    const float* glove    = (const float*)d_in[2];
    const float* cemb     = (const float*)d_in[3];
    const float* W_ih     = (const float*)d_in[4];
    const float* W_hh     = (const float*)d_in[5];
    const float* b_ih     = (const float*)d_in[6];
    const float* b_hh     = (const float*)d_in[7];
    const float* fc1_w    = (const float*)d_in[8];
    const float* fc1_b    = (const float*)d_in[9];
    const float* fc2_w    = (const float*)d_in[10];
    const float* fc2_b    = (const float*)d_in[11];
    float* out = (float*)d_out;

    const int smem_bytes =
        (KTOT * XH_STRIDE + 2 * KT * CHAR_HID * 4) * (int)sizeof(float)   // xh + 2 weight tiles
        + 512 * (int)sizeof(int)                                          // scidx
        + 512 * (int)sizeof(float);                                       // ssum
    cudaFuncSetAttribute(lstm_kernel,
                         cudaFuncAttributeMaxDynamicSharedMemorySize, smem_bytes);

    prep_kernel<<<128, 256>>>(W_ih, W_hh, b_ih, b_hh);
    glove_kernel<<<NBLK, 320>>>(word_idx, glove);
    lstm_kernel<<<NBLK, 512, smem_bytes>>>(char_idx, cemb);
    avg_kernel<<<107, 128>>>();
    fc1_kernel<<<64, 256>>>(fc1_w, fc1_b);
    fc2_kernel<<<1, 512>>>(fc2_w, fc2_b, out);
}